// round 1
// baseline (speedup 1.0000x reference)
#include <cuda_runtime.h>
#include <cuda_bf16.h>

// PCEN: x (32,1,128,8000) fp32.
// Per row (B*C*F = 4096): IIR smoother along T, then pointwise transform.
// One CTA per row; blocked parallel scan for the linear recurrence.

#define T_LEN     8000
#define F_BANDS   128
#define NTHREADS  256
#define CH        32
#define NCHUNK    250   // 8000 / 32
#define SH_PITCH  257   // bank-conflict-free pitch

__device__ __forceinline__ float flg2(float x) {
    float y; asm("lg2.approx.f32 %0, %1;" : "=f"(y) : "f"(x)); return y;
}
__device__ __forceinline__ float fex2(float x) {
    float y; asm("ex2.approx.f32 %0, %1;" : "=f"(y) : "f"(x)); return y;
}

__global__ __launch_bounds__(NTHREADS)
void pcen_kernel(const float* __restrict__ x,
                 const float* __restrict__ log_s,
                 const float* __restrict__ log_alpha,
                 const float* __restrict__ log_delta,
                 const float* __restrict__ log_r,
                 float* __restrict__ out)
{
    // swizzled row buffer: element t lives at sh[(t&31)*SH_PITCH + (t>>5)]
    __shared__ float sh[CH * SH_PITCH];      // 8224 floats
    __shared__ float sm_m[NTHREADS];
    __shared__ float sm_c[NTHREADS];

    const int row  = blockIdx.x;
    const int band = row % F_BANDS;          // C == 1
    const int tid  = threadIdx.x;

    const float s      = expf(log_s[band]);
    const float a      = 1.0f - s;
    const float alpha  = expf(log_alpha[band]);
    const float nalpha = -alpha;
    const float delta  = expf(log_delta[band]);
    const float r      = expf(log_r[band]);
    const float dr     = powf(delta, r);
    const float eps    = 1e-6f;

    const float4* __restrict__ xrow = reinterpret_cast<const float4*>(x + (size_t)row * T_LEN);
    float4* __restrict__ orow       = reinterpret_cast<float4*>(out + (size_t)row * T_LEN);

    // ---- load: global (coalesced float4) -> swizzled shared ----
    for (int v = tid; v < T_LEN / 4; v += NTHREADS) {
        float4 q = xrow[v];
        int t  = v * 4;
        int i0 = t >> 5;        // chunk id (constant across the 4 elems: t%32 <= 28)
        int k0 = t & 31;
        sh[(k0 + 0) * SH_PITCH + i0] = q.x;
        sh[(k0 + 1) * SH_PITCH + i0] = q.y;
        sh[(k0 + 2) * SH_PITCH + i0] = q.z;
        sh[(k0 + 3) * SH_PITCH + i0] = q.w;
    }
    __syncthreads();

    // ---- pass 1: local IIR over own chunk; emit (m, c) with f_end = m*f_in + c ----
    float m, c;
    if (tid == 0) {
        float f = sh[0];                         // f[0] = x[0]
        #pragma unroll 8
        for (int k = 1; k < CH; k++)
            f = a * f + s * sh[k * SH_PITCH];
        m = 0.0f; c = f;
    } else if (tid < NCHUNK) {
        float f = 0.0f;
        #pragma unroll 8
        for (int k = 0; k < CH; k++)
            f = a * f + s * sh[k * SH_PITCH + tid];
        float a2 = a * a, a4 = a2 * a2, a8 = a4 * a4, a16 = a8 * a8;
        m = a16 * a16;                           // a^32
        c = f;
    } else {
        m = 1.0f; c = 0.0f;                      // identity
    }

    sm_m[tid] = m; sm_c[tid] = c;
    __syncthreads();

    // ---- inclusive Hillis-Steele scan of (m, c) ----
    #pragma unroll
    for (int off = 1; off < NTHREADS; off <<= 1) {
        float pm = 0.0f, pc = 0.0f;
        if (tid >= off) { pm = sm_m[tid - off]; pc = sm_c[tid - off]; }
        __syncthreads();
        if (tid >= off) {
            c = c + m * pc;
            m = m * pm;
            sm_m[tid] = m; sm_c[tid] = c;
        }
        __syncthreads();
    }

    const float fin = (tid > 0) ? sm_c[tid - 1] : 0.0f;

    // ---- pass 2: replay with correct carry, fuse PCEN transform, write in place ----
    if (tid < NCHUNK) {
        float f = fin;
        #pragma unroll 8
        for (int k = 0; k < CH; k++) {
            float xv = sh[k * SH_PITCH + tid];
            if (tid == 0 && k == 0) f = xv;
            else                    f = a * f + s * xv;
            float w = fex2(nalpha * flg2(eps + f));   // (eps+f)^(-alpha)
            float q = xv * w + delta;
            float o = fex2(r * flg2(q)) - dr;         // q^r - delta^r
            sh[k * SH_PITCH + tid] = o;
        }
    }
    __syncthreads();

    // ---- store: swizzled shared -> global (coalesced float4) ----
    for (int v = tid; v < T_LEN / 4; v += NTHREADS) {
        int t  = v * 4;
        int i0 = t >> 5;
        int k0 = t & 31;
        float4 q;
        q.x = sh[(k0 + 0) * SH_PITCH + i0];
        q.y = sh[(k0 + 1) * SH_PITCH + i0];
        q.z = sh[(k0 + 2) * SH_PITCH + i0];
        q.w = sh[(k0 + 3) * SH_PITCH + i0];
        orow[v] = q;
    }
}

extern "C" void kernel_launch(void* const* d_in, const int* in_sizes, int n_in,
                              void* d_out, int out_size) {
    const float* x         = (const float*)d_in[0];
    const float* log_s     = (const float*)d_in[1];
    const float* log_alpha = (const float*)d_in[2];
    const float* log_delta = (const float*)d_in[3];
    const float* log_r     = (const float*)d_in[4];
    float* out = (float*)d_out;

    int rows = out_size / T_LEN;   // 4096
    pcen_kernel<<<rows, NTHREADS>>>(x, log_s, log_alpha, log_delta, log_r, out);
}

// round 11
// speedup vs baseline: 1.1958x; 1.1958x over previous
#include <cuda_runtime.h>
#include <cuda_bf16.h>

// PCEN on x (32,1,128,8000) fp32.
// One CTA per row (4096 rows). Register-resident blocked scan, V=8:
//   - each thread owns 8 consecutive elements (two adjacent float4 loads)
//   - local affine fold (m=a^8) -> 5-round warp shuffle scan -> 8-warp smem scan
//   - scalar carry chains the 4 tiles of 2048 elements per row
//   - next tile's loads issued before current tile's compute (pipelined)
// No data staging in shared memory; streaming cache hints (data > L2).

#define T_LEN    8000
#define F_BANDS  128
#define NT       256
#define NVEC     (T_LEN / 4)                   // 2000 float4 per row
#define NPAIR    (NVEC / 2)                    // 1000 float4-pairs per row
#define NTILES   ((NPAIR + NT - 1) / NT)       // 4 tiles

__device__ __forceinline__ float flg2(float v) {
    float y; asm("lg2.approx.f32 %0, %1;" : "=f"(y) : "f"(v)); return y;
}
__device__ __forceinline__ float fex2(float v) {
    float y; asm("ex2.approx.f32 %0, %1;" : "=f"(y) : "f"(v)); return y;
}

__global__ __launch_bounds__(NT)
void pcen_kernel(const float* __restrict__ x,
                 const float* __restrict__ log_s,
                 const float* __restrict__ log_alpha,
                 const float* __restrict__ log_delta,
                 const float* __restrict__ log_r,
                 float* __restrict__ out)
{
    __shared__ float sm_m[2][8];
    __shared__ float sm_c[2][8];

    const int row  = blockIdx.x;
    const int band = row % F_BANDS;            // C == 1
    const int tid  = threadIdx.x;
    const int lane = tid & 31;
    const int warp = tid >> 5;

    const float s      = expf(log_s[band]);
    const float a      = 1.0f - s;
    const float a4     = (a * a) * (a * a);
    const float a8     = a4 * a4;
    const float alpha  = expf(log_alpha[band]);
    const float nalpha = -alpha;
    const float delta  = expf(log_delta[band]);
    const float r      = expf(log_r[band]);
    const float dr     = powf(delta, r);
    const float eps    = 1e-6f;

    const float4* __restrict__ xr = reinterpret_cast<const float4*>(x + (size_t)row * T_LEN);
    float4* __restrict__ orow     = reinterpret_cast<float4*>(out + (size_t)row * T_LEN);

    float fc = 0.0f;                           // smoother value at end of previous tile

    // prefetch tile 0 (pair tid -> float4 indices 2*tid, 2*tid+1)
    float4 q0 = make_float4(0.f,0.f,0.f,0.f), q1 = q0;
    if (tid < NPAIR) {
        q0 = __ldcs(&xr[2 * tid]);
        q1 = __ldcs(&xr[2 * tid + 1]);
    }

    for (int tile = 0; tile < NTILES; tile++) {
        const int  pidx   = tile * NT + tid;   // pair index within row
        const bool active = (pidx < NPAIR);
        const bool first  = (tile == 0) && (tid == 0);

        // issue next tile's loads early (independent of everything below)
        float4 n0 = make_float4(0.f,0.f,0.f,0.f), n1 = n0;
        const int pnext = pidx + NT;
        if (tile + 1 < NTILES && pnext < NPAIR) {
            n0 = __ldcs(&xr[2 * pnext]);
            n1 = __ldcs(&xr[2 * pnext + 1]);
        }

        // local affine transform over 8 elems: f_out = m*f_in + c
        float m, c;
        if (active) {
            if (first) {                        // f[0] = x[0]
                c = q0.x; m = 0.0f;
            } else {
                c = s * q0.x; m = a8;
            }
            c = a * c + s * q0.y;
            c = a * c + s * q0.z;
            c = a * c + s * q0.w;
            c = a * c + s * q1.x;
            c = a * c + s * q1.y;
            c = a * c + s * q1.z;
            c = a * c + s * q1.w;
        } else { m = 1.0f; c = 0.0f; }          // identity for inactive lanes

        // inclusive warp scan of (m, c) under composition (later ∘ earlier)
        float mi = m, ci = c;
        #pragma unroll
        for (int off = 1; off < 32; off <<= 1) {
            float pm = __shfl_up_sync(0xffffffffu, mi, off);
            float pc = __shfl_up_sync(0xffffffffu, ci, off);
            if (lane >= off) { ci = ci + mi * pc; mi = mi * pm; }
        }

        const int buf = tile & 1;
        if (lane == 31) { sm_m[buf][warp] = mi; sm_c[buf][warp] = ci; }
        __syncthreads();

        // warp-exclusive prefix (Mw,Cw) and tile total (Mt,Ct), redundant per thread
        float Mw = 1.0f, Cw = 0.0f, Mt = 1.0f, Ct = 0.0f;
        #pragma unroll
        for (int w = 0; w < 8; w++) {
            float wm = sm_m[buf][w], wc = sm_c[buf][w];
            if (w < warp) { Cw = wc + wm * Cw; Mw = wm * Mw; }
            Ct = wc + wm * Ct; Mt = wm * Mt;
        }

        // thread-exclusive within warp
        float me = __shfl_up_sync(0xffffffffu, mi, 1);
        float ce = __shfl_up_sync(0xffffffffu, ci, 1);
        if (lane == 0) { me = 1.0f; ce = 0.0f; }

        // smoother value entering this thread's 8 elements
        const float Mp  = me * Mw;
        const float Cp  = ce + me * Cw;
        const float fin = Mp * fc + Cp;

        // advance row carry
        fc = Mt * fc + Ct;

        if (active) {
            float f0 = first ? q0.x : (a * fin + s * q0.x);
            float f1 = a * f0 + s * q0.y;
            float f2 = a * f1 + s * q0.z;
            float f3 = a * f2 + s * q0.w;
            float f4 = a * f3 + s * q1.x;
            float f5 = a * f4 + s * q1.y;
            float f6 = a * f5 + s * q1.z;
            float f7 = a * f6 + s * q1.w;

            float4 o0, o1;
            {
                float w0 = fex2(nalpha * flg2(eps + f0));
                float w1 = fex2(nalpha * flg2(eps + f1));
                float w2 = fex2(nalpha * flg2(eps + f2));
                float w3 = fex2(nalpha * flg2(eps + f3));
                float w4 = fex2(nalpha * flg2(eps + f4));
                float w5 = fex2(nalpha * flg2(eps + f5));
                float w6 = fex2(nalpha * flg2(eps + f6));
                float w7 = fex2(nalpha * flg2(eps + f7));
                o0.x = fex2(r * flg2(q0.x * w0 + delta)) - dr;
                o0.y = fex2(r * flg2(q0.y * w1 + delta)) - dr;
                o0.z = fex2(r * flg2(q0.z * w2 + delta)) - dr;
                o0.w = fex2(r * flg2(q0.w * w3 + delta)) - dr;
                o1.x = fex2(r * flg2(q1.x * w4 + delta)) - dr;
                o1.y = fex2(r * flg2(q1.y * w5 + delta)) - dr;
                o1.z = fex2(r * flg2(q1.z * w6 + delta)) - dr;
                o1.w = fex2(r * flg2(q1.w * w7 + delta)) - dr;
            }
            __stcs(&orow[2 * pidx],     o0);
            __stcs(&orow[2 * pidx + 1], o1);
        }

        q0 = n0; q1 = n1;
    }
}

extern "C" void kernel_launch(void* const* d_in, const int* in_sizes, int n_in,
                              void* d_out, int out_size) {
    const float* x         = (const float*)d_in[0];
    const float* log_s     = (const float*)d_in[1];
    const float* log_alpha = (const float*)d_in[2];
    const float* log_delta = (const float*)d_in[3];
    const float* log_r     = (const float*)d_in[4];
    float* out = (float*)d_out;

    int rows = out_size / T_LEN;   // 4096
    pcen_kernel<<<rows, NT>>>(x, log_s, log_alpha, log_delta, log_r, out);
}

// round 13
// speedup vs baseline: 1.2591x; 1.0529x over previous
#include <cuda_runtime.h>
#include <cuda_bf16.h>

// PCEN on x (32,1,128,8000) fp32.
// One CTA per row (4096 rows). Register-resident blocked scan, V=8.
// R12 changes vs R11 (issue-bound at 81.7%): uniform-recurrence init
// (fc = x[0] removes all `first` special cases), fused snapshot prefix
// loop, full tile unroll so only the last tile carries predication.

#define T_LEN    8000
#define F_BANDS  128
#define NT       256
#define NPAIR    (T_LEN / 8)                   // 1000 groups of 8 elems
#define NTILES   ((NPAIR + NT - 1) / NT)       // 4 tiles
#define LAST_N   (NPAIR - (NTILES - 1) * NT)   // 232 active threads in last tile

__device__ __forceinline__ float flg2(float v) {
    float y; asm("lg2.approx.f32 %0, %1;" : "=f"(y) : "f"(v)); return y;
}
__device__ __forceinline__ float fex2(float v) {
    float y; asm("ex2.approx.f32 %0, %1;" : "=f"(y) : "f"(v)); return y;
}

__global__ __launch_bounds__(NT)
void pcen_kernel(const float* __restrict__ x,
                 const float* __restrict__ log_s,
                 const float* __restrict__ log_alpha,
                 const float* __restrict__ log_delta,
                 const float* __restrict__ log_r,
                 float* __restrict__ out)
{
    __shared__ float sm_m[NTILES][8];
    __shared__ float sm_c[NTILES][8];

    const int row  = blockIdx.x;
    const int band = row % F_BANDS;            // C == 1
    const int tid  = threadIdx.x;
    const int lane = tid & 31;
    const int warp = tid >> 5;

    const float s      = expf(log_s[band]);
    const float a      = 1.0f - s;
    const float a4     = (a * a) * (a * a);
    const float a8     = a4 * a4;
    const float nalpha = -expf(log_alpha[band]);
    const float delta  = expf(log_delta[band]);
    const float r      = expf(log_r[band]);
    const float dr     = powf(delta, r);
    const float eps    = 1e-6f;

    const float* __restrict__ xp  = x + (size_t)row * T_LEN;
    float* __restrict__ op        = out + (size_t)row * T_LEN;
    const float4* __restrict__ xr = reinterpret_cast<const float4*>(xp);
    float4* __restrict__ orow     = reinterpret_cast<float4*>(op);

    // Uniform-recurrence init: with pre-state f_{-1} = x[0],
    // f[0] = a*x[0] + s*x[0] = x[0]. No special case anywhere below.
    float fc = __ldg(&xp[0]);

    // prefetch tile 0 (thread owns elements [8*pidx, 8*pidx+8))
    float4 q0 = __ldcs(&xr[2 * tid]);
    float4 q1 = __ldcs(&xr[2 * tid + 1]);

    #pragma unroll
    for (int tile = 0; tile < NTILES; tile++) {
        const int  pidx   = tile * NT + tid;
        const bool active = (tile < NTILES - 1) || (tid < LAST_N);  // const for tiles 0-2

        // issue next tile's loads early (independent of everything below)
        float4 n0 = make_float4(0.f, 0.f, 0.f, 0.f), n1 = n0;
        if (tile + 1 < NTILES) {
            const int pn = pidx + NT;
            if ((tile + 2 < NTILES) || (pn < NPAIR)) {  // const-true except tile 2
                n0 = __ldcs(&xr[2 * pn]);
                n1 = __ldcs(&xr[2 * pn + 1]);
            }
        }

        // local affine fold over 8 elems: f_out = mi*f_in + ci (uniform, no branches)
        float mi, ci;
        if (active) {
            float cl = s * q0.x;
            cl = a * cl + s * q0.y;
            cl = a * cl + s * q0.z;
            cl = a * cl + s * q0.w;
            cl = a * cl + s * q1.x;
            cl = a * cl + s * q1.y;
            cl = a * cl + s * q1.z;
            cl = a * cl + s * q1.w;
            mi = a8; ci = cl;
        } else { mi = 1.0f; ci = 0.0f; }       // identity for inactive lanes (tile 3 only)

        // inclusive warp scan of (mi, ci) under composition (later ∘ earlier)
        #pragma unroll
        for (int off = 1; off < 32; off <<= 1) {
            float pm = __shfl_up_sync(0xffffffffu, mi, off);
            float pc = __shfl_up_sync(0xffffffffu, ci, off);
            if (lane >= off) { ci = ci + mi * pc; mi = mi * pm; }
        }

        if (lane == 31) { sm_m[tile][warp] = mi; sm_c[tile][warp] = ci; }
        __syncthreads();

        // single snapshot loop: warp-exclusive prefix (Mw,Cw) + tile total (M,C)
        float M = 1.0f, C = 0.0f, Mw = 1.0f, Cw = 0.0f;
        #pragma unroll
        for (int w = 0; w < 8; w++) {
            if (w == warp) { Mw = M; Cw = C; }
            const float wm = sm_m[tile][w], wc = sm_c[tile][w];
            C = wc + wm * C;
            M = wm * M;
        }

        // thread-exclusive within warp
        float me = __shfl_up_sync(0xffffffffu, mi, 1);
        float ce = __shfl_up_sync(0xffffffffu, ci, 1);
        if (lane == 0) { me = 1.0f; ce = 0.0f; }

        // smoother value entering this thread's 8 elements, then advance row carry
        const float fin = (me * Mw) * fc + (ce + me * Cw);
        fc = M * fc + C;

        if (active) {
            float f = fin;
            float4 o0, o1;
            f = a * f + s * q0.x;  o0.x = fex2(r * flg2(q0.x * fex2(nalpha * flg2(eps + f)) + delta)) - dr;
            f = a * f + s * q0.y;  o0.y = fex2(r * flg2(q0.y * fex2(nalpha * flg2(eps + f)) + delta)) - dr;
            f = a * f + s * q0.z;  o0.z = fex2(r * flg2(q0.z * fex2(nalpha * flg2(eps + f)) + delta)) - dr;
            f = a * f + s * q0.w;  o0.w = fex2(r * flg2(q0.w * fex2(nalpha * flg2(eps + f)) + delta)) - dr;
            f = a * f + s * q1.x;  o1.x = fex2(r * flg2(q1.x * fex2(nalpha * flg2(eps + f)) + delta)) - dr;
            f = a * f + s * q1.y;  o1.y = fex2(r * flg2(q1.y * fex2(nalpha * flg2(eps + f)) + delta)) - dr;
            f = a * f + s * q1.z;  o1.z = fex2(r * flg2(q1.z * fex2(nalpha * flg2(eps + f)) + delta)) - dr;
            f = a * f + s * q1.w;  o1.w = fex2(r * flg2(q1.w * fex2(nalpha * flg2(eps + f)) + delta)) - dr;

            __stcs(&orow[2 * pidx],     o0);
            __stcs(&orow[2 * pidx + 1], o1);
        }

        if (tile + 1 < NTILES) { q0 = n0; q1 = n1; }
    }
}

extern "C" void kernel_launch(void* const* d_in, const int* in_sizes, int n_in,
                              void* d_out, int out_size) {
    const float* x         = (const float*)d_in[0];
    const float* log_s     = (const float*)d_in[1];
    const float* log_alpha = (const float*)d_in[2];
    const float* log_delta = (const float*)d_in[3];
    const float* log_r     = (const float*)d_in[4];
    float* out = (float*)d_out;

    int rows = out_size / T_LEN;   // 4096
    pcen_kernel<<<rows, NT>>>(x, log_s, log_alpha, log_delta, log_r, out);
}